// round 1
// baseline (speedup 1.0000x reference)
#include <cuda_runtime.h>
#include <math.h>

#define D_MODEL 1024
#define SEQ     2048
#define NHEADS  16
#define HDIM    64
#define BATCH   4

// Scratch (allocation-free rule: __device__ globals)
__device__ float g_Q[(size_t)BATCH * SEQ * D_MODEL];
__device__ float g_K[(size_t)BATCH * SEQ * D_MODEL];
__device__ float g_V[(size_t)BATCH * SEQ * D_MODEL];
__device__ float g_A[(size_t)BATCH * SEQ * D_MODEL];

// ---------------------------------------------------------------------------
// GEMM: C[M,N] = A[M,K] @ W[K,N] + bias, optional fused RoPE on output rows.
// Tiles: 64x64, BK=16, 256 threads, 4x4 per thread.
// ---------------------------------------------------------------------------
#define GTS 64
#define GTK 16
#define GAS 68

__global__ __launch_bounds__(256) void gemm_bias_rope(
    const float* __restrict__ A, const float* __restrict__ W,
    const float* __restrict__ bias, float* __restrict__ C,
    int M, int N, int K, int applyRope)
{
    __shared__ float As[GTK][GAS];
    __shared__ float Bs[GTK][GAS];
    const int t  = threadIdx.x;
    const int tx = t & 15;
    const int ty = t >> 4;
    const int m0 = blockIdx.y * GTS;
    const int n0 = blockIdx.x * GTS;

    const int arow = t >> 2;          // 0..63
    const int acol = (t & 3) << 2;    // 0,4,8,12
    const int brow = t >> 4;          // 0..15
    const int bcol = (t & 15) << 2;   // 0..60

    const float* Ap = A + (size_t)(m0 + arow) * K + acol;
    const float* Bp = W + (size_t)brow * N + n0 + bcol;

    float acc[4][4];
#pragma unroll
    for (int i = 0; i < 4; i++)
#pragma unroll
        for (int j = 0; j < 4; j++) acc[i][j] = 0.f;

    for (int k0 = 0; k0 < K; k0 += GTK) {
        float4 av = *(const float4*)(Ap + k0);
        float4 bv = *(const float4*)(Bp + (size_t)k0 * N);
        As[acol + 0][arow] = av.x;
        As[acol + 1][arow] = av.y;
        As[acol + 2][arow] = av.z;
        As[acol + 3][arow] = av.w;
        *(float4*)&Bs[brow][bcol] = bv;
        __syncthreads();
#pragma unroll
        for (int kk = 0; kk < GTK; kk++) {
            float4 a = *(const float4*)&As[kk][ty << 2];
            float4 b = *(const float4*)&Bs[kk][tx << 2];
            acc[0][0] += a.x * b.x; acc[0][1] += a.x * b.y; acc[0][2] += a.x * b.z; acc[0][3] += a.x * b.w;
            acc[1][0] += a.y * b.x; acc[1][1] += a.y * b.y; acc[1][2] += a.y * b.z; acc[1][3] += a.y * b.w;
            acc[2][0] += a.z * b.x; acc[2][1] += a.z * b.y; acc[2][2] += a.z * b.z; acc[2][3] += a.z * b.w;
            acc[3][0] += a.w * b.x; acc[3][1] += a.w * b.y; acc[3][2] += a.w * b.z; acc[3][3] += a.w * b.w;
        }
        __syncthreads();
    }

    const float4 bb = *(const float4*)(bias + n0 + (tx << 2));
    // -log2(10000)/512
    const float NEG_L2B = -0.02595256324130752f;
#pragma unroll
    for (int i = 0; i < 4; i++) {
        const int row = m0 + (ty << 2) + i;
        float v0 = acc[i][0] + bb.x;
        float v1 = acc[i][1] + bb.y;
        float v2 = acc[i][2] + bb.z;
        float v3 = acc[i][3] + bb.w;
        if (applyRope) {
            const float pos = (float)(row & (SEQ - 1));
            const int c0 = n0 + (tx << 2);     // even
            const int p0 = c0 >> 1;
            const float f0 = exp2f((float)p0 * NEG_L2B);
            const float f1 = exp2f((float)(p0 + 1) * NEG_L2B);
            float s0, c_0, s1, c_1;
            sincosf(pos * f0, &s0, &c_0);
            sincosf(pos * f1, &s1, &c_1);
            const float r0 = v0 * c_0 - v1 * s0;
            const float r1 = v0 * s0 + v1 * c_0;
            const float r2 = v2 * c_1 - v3 * s1;
            const float r3 = v2 * s1 + v3 * c_1;
            v0 = r0; v1 = r1; v2 = r2; v3 = r3;
        }
        float4 o; o.x = v0; o.y = v1; o.z = v2; o.w = v3;
        *(float4*)(C + (size_t)row * N + n0 + (tx << 2)) = o;
    }
}

// ---------------------------------------------------------------------------
// Flash attention, fp32, causal. BM=BN=64, hd=64. 256 threads.
// 4 threads per query row (cg = t&3 owns 16 key-cols / 16 hd-cols).
// P exchanged via shfl (no P smem).
// ---------------------------------------------------------------------------
#define FBM 64
#define FBN 64
#define QSTR 66
#define KSTR 68
#define VSTR 68
#define FLASH_SMEM ((FBM * QSTR + HDIM * KSTR + FBN * VSTR) * 4)

__global__ __launch_bounds__(256) void flash_attn(
    const float* __restrict__ Q, const float* __restrict__ K,
    const float* __restrict__ V, float* __restrict__ O, int S)
{
    extern __shared__ float sm[];
    float* Qs = sm;                       // [FBM][QSTR]
    float* Kt = Qs + FBM * QSTR;          // [HDIM][KSTR]  (transposed: Kt[kk][col])
    float* Vs = Kt + HDIM * KSTR;         // [FBN][VSTR]

    const int t     = threadIdx.x;
    const int row   = t >> 2;             // 0..63
    const int cg    = t & 3;              // 0..3
    const int lane4 = t & 28;             // lane base of this row's 4-lane group

    const int qt = blockIdx.x, h = blockIdx.y, b = blockIdx.z;
    const int q0 = qt * FBM;
    const size_t Dm = D_MODEL;
    const float* Qb = Q + (size_t)b * S * Dm + (size_t)h * HDIM;
    const float* Kb = K + (size_t)b * S * Dm + (size_t)h * HDIM;
    const float* Vb = V + (size_t)b * S * Dm + (size_t)h * HDIM;
    float*       Ob = O + (size_t)b * S * Dm + (size_t)h * HDIM;

    // Load Q tile, pre-scaled by 1/sqrt(hd)
    for (int idx = t; idx < FBM * 16; idx += 256) {
        const int r = idx >> 4, c4 = (idx & 15) << 2;
        float4 v = *(const float4*)(Qb + (size_t)(q0 + r) * Dm + c4);
        Qs[r * QSTR + c4 + 0] = v.x * 0.125f;
        Qs[r * QSTR + c4 + 1] = v.y * 0.125f;
        Qs[r * QSTR + c4 + 2] = v.z * 0.125f;
        Qs[r * QSTR + c4 + 3] = v.w * 0.125f;
    }

    float m_i = -1e30f, l_i = 0.f;
    float Oc[16];
#pragma unroll
    for (int c = 0; c < 16; c++) Oc[c] = 0.f;

    for (int kt = 0; kt <= qt; kt++) {
        const int k0 = kt * FBN;
        __syncthreads();   // protect smem from previous iteration's readers
        for (int idx = t; idx < FBN * 16; idx += 256) {
            const int r = idx >> 4, c4 = (idx & 15) << 2;
            float4 kv = *(const float4*)(Kb + (size_t)(k0 + r) * Dm + c4);
            Kt[(c4 + 0) * KSTR + r] = kv.x;
            Kt[(c4 + 1) * KSTR + r] = kv.y;
            Kt[(c4 + 2) * KSTR + r] = kv.z;
            Kt[(c4 + 3) * KSTR + r] = kv.w;
            float4 vv = *(const float4*)(Vb + (size_t)(k0 + r) * Dm + c4);
            *(float4*)&Vs[r * VSTR + c4] = vv;
        }
        __syncthreads();

        // --- S = Q K^T for this thread's 16 key-cols ---
        float acc[16];
#pragma unroll
        for (int c = 0; c < 16; c++) acc[c] = 0.f;
#pragma unroll 8
        for (int kk = 0; kk < HDIM; kk++) {
            const float q = Qs[row * QSTR + kk];
            const float* kp = &Kt[kk * KSTR + (cg << 4)];
            const float4 b0 = *(const float4*)(kp + 0);
            const float4 b1 = *(const float4*)(kp + 4);
            const float4 b2 = *(const float4*)(kp + 8);
            const float4 b3 = *(const float4*)(kp + 12);
            acc[0]  += q * b0.x; acc[1]  += q * b0.y; acc[2]  += q * b0.z; acc[3]  += q * b0.w;
            acc[4]  += q * b1.x; acc[5]  += q * b1.y; acc[6]  += q * b1.z; acc[7]  += q * b1.w;
            acc[8]  += q * b2.x; acc[9]  += q * b2.y; acc[10] += q * b2.z; acc[11] += q * b2.w;
            acc[12] += q * b3.x; acc[13] += q * b3.y; acc[14] += q * b3.z; acc[15] += q * b3.w;
        }

        if (kt == qt) {   // causal mask on diagonal tile
#pragma unroll
            for (int c = 0; c < 16; c++)
                if (k0 + (cg << 4) + c > q0 + row) acc[c] = -1e30f;
        }

        // --- online softmax (reduce across the row's 4 lanes) ---
        float mloc = acc[0];
#pragma unroll
        for (int c = 1; c < 16; c++) mloc = fmaxf(mloc, acc[c]);
        mloc = fmaxf(mloc, __shfl_xor_sync(0xffffffffu, mloc, 1));
        mloc = fmaxf(mloc, __shfl_xor_sync(0xffffffffu, mloc, 2));
        const float m_new = fmaxf(m_i, mloc);
        const float alpha = __expf(m_i - m_new);
        float lsum = 0.f;
#pragma unroll
        for (int c = 0; c < 16; c++) { acc[c] = __expf(acc[c] - m_new); lsum += acc[c]; }
        lsum += __shfl_xor_sync(0xffffffffu, lsum, 1);
        lsum += __shfl_xor_sync(0xffffffffu, lsum, 2);
        l_i = l_i * alpha + lsum;
        m_i = m_new;
#pragma unroll
        for (int c = 0; c < 16; c++) Oc[c] *= alpha;

        // --- O += P V ; P broadcast via shfl from the lane owning that col ---
#pragma unroll 1
        for (int grp = 0; grp < 4; grp++) {
            const int src = lane4 | grp;
#pragma unroll
            for (int jj = 0; jj < 16; jj++) {
                const float p = __shfl_sync(0xffffffffu, acc[jj], src);
                const float* vp = &Vs[(grp * 16 + jj) * VSTR + (cg << 4)];
                const float4 v0 = *(const float4*)(vp + 0);
                const float4 v1 = *(const float4*)(vp + 4);
                const float4 v2 = *(const float4*)(vp + 8);
                const float4 v3 = *(const float4*)(vp + 12);
                Oc[0]  += p * v0.x; Oc[1]  += p * v0.y; Oc[2]  += p * v0.z; Oc[3]  += p * v0.w;
                Oc[4]  += p * v1.x; Oc[5]  += p * v1.y; Oc[6]  += p * v1.z; Oc[7]  += p * v1.w;
                Oc[8]  += p * v2.x; Oc[9]  += p * v2.y; Oc[10] += p * v2.z; Oc[11] += p * v2.w;
                Oc[12] += p * v3.x; Oc[13] += p * v3.y; Oc[14] += p * v3.z; Oc[15] += p * v3.w;
            }
        }
    }

    const float inv_l = 1.f / l_i;
    float* op = Ob + (size_t)(q0 + row) * Dm + (cg << 4);
    float4 o;
    o.x = Oc[0] * inv_l;  o.y = Oc[1] * inv_l;  o.z = Oc[2] * inv_l;  o.w = Oc[3] * inv_l;
    *(float4*)(op + 0) = o;
    o.x = Oc[4] * inv_l;  o.y = Oc[5] * inv_l;  o.z = Oc[6] * inv_l;  o.w = Oc[7] * inv_l;
    *(float4*)(op + 4) = o;
    o.x = Oc[8] * inv_l;  o.y = Oc[9] * inv_l;  o.z = Oc[10] * inv_l; o.w = Oc[11] * inv_l;
    *(float4*)(op + 8) = o;
    o.x = Oc[12] * inv_l; o.y = Oc[13] * inv_l; o.z = Oc[14] * inv_l; o.w = Oc[15] * inv_l;
    *(float4*)(op + 12) = o;
}

// ---------------------------------------------------------------------------
extern "C" void kernel_launch(void* const* d_in, const int* in_sizes, int n_in,
                              void* d_out, int out_size)
{
    const float* X  = (const float*)d_in[0];
    const float* Wq = (const float*)d_in[1];
    const float* bq = (const float*)d_in[2];
    const float* Wk = (const float*)d_in[3];
    const float* bk = (const float*)d_in[4];
    const float* Wv = (const float*)d_in[5];
    const float* bv = (const float*)d_in[6];
    const float* Wo = (const float*)d_in[7];
    const float* bo = (const float*)d_in[8];
    float* out = (float*)d_out;

    const int M  = in_sizes[0] / D_MODEL;   // 8192
    const int Bb = M / SEQ;                 // 4

    float *qp, *kp, *vp, *ap;
    cudaGetSymbolAddress((void**)&qp, g_Q);
    cudaGetSymbolAddress((void**)&kp, g_K);
    cudaGetSymbolAddress((void**)&vp, g_V);
    cudaGetSymbolAddress((void**)&ap, g_A);

    dim3 gblk(D_MODEL / GTS, M / GTS);
    gemm_bias_rope<<<gblk, 256>>>(X, Wq, bq, qp, M, D_MODEL, D_MODEL, 1);
    gemm_bias_rope<<<gblk, 256>>>(X, Wk, bk, kp, M, D_MODEL, D_MODEL, 1);
    gemm_bias_rope<<<gblk, 256>>>(X, Wv, bv, vp, M, D_MODEL, D_MODEL, 0);

    cudaFuncSetAttribute(flash_attn, cudaFuncAttributeMaxDynamicSharedMemorySize,
                         FLASH_SMEM);
    flash_attn<<<dim3(SEQ / FBM, NHEADS, Bb), 256, FLASH_SMEM>>>(qp, kp, vp, ap, SEQ);

    gemm_bias_rope<<<gblk, 256>>>(ap, Wo, bo, out, M, D_MODEL, D_MODEL, 0);
}

// round 2
// speedup vs baseline: 2.3180x; 2.3180x over previous
#include <cuda_runtime.h>
#include <math.h>

#define D_MODEL 1024
#define SEQ     2048
#define NHEADS  16
#define HDIM    64
#define BATCH   4
#define MTOT    (BATCH*SEQ)

// Scratch (allocation-free rule: __device__ globals)
__device__ float g_Q[(size_t)MTOT * D_MODEL];
__device__ float g_K[(size_t)MTOT * D_MODEL];
__device__ float g_V[(size_t)MTOT * D_MODEL];
__device__ float g_A[(size_t)MTOT * D_MODEL];

// ===========================================================================
// tf32 tensor-core GEMM: C[M,1024] = A[M,1024] @ W[1024,1024] + bias (+RoPE)
// BM=128 BN=128 BK=32, 256 threads (8 warps as 2m x 4n), warp tile 64x32,
// mma.m16n8k8 tiles 4x4 per warp. Double-buffered smem.
// Bank-conflict-free layouts: As[m][k] stride 36, Bs[k][n] stride 136.
// ===========================================================================
#define BM 128
#define BN 128
#define BKC 32
#define AST 36
#define BST 136
#define ASZ (BM*AST)
#define BSZ (BKC*BST)
#define GEMM_SMEM ((2*ASZ + 2*BSZ)*4)

__device__ __forceinline__ unsigned to_tf32(float x) {
    unsigned r; asm("cvt.rna.tf32.f32 %0, %1;" : "=r"(r) : "f"(x)); return r;
}
__device__ __forceinline__ void mma_tf32(float* d, const unsigned* a, const unsigned* b) {
    asm volatile(
        "mma.sync.aligned.m16n8k8.row.col.f32.tf32.tf32.f32 "
        "{%0,%1,%2,%3}, {%4,%5,%6,%7}, {%8,%9}, {%0,%1,%2,%3};\n"
        : "+f"(d[0]), "+f"(d[1]), "+f"(d[2]), "+f"(d[3])
        : "r"(a[0]), "r"(a[1]), "r"(a[2]), "r"(a[3]), "r"(b[0]), "r"(b[1]));
}

__global__ __launch_bounds__(256) void gemm_tf32(
    const float* __restrict__ A, const float* __restrict__ W,
    const float* __restrict__ bias, float* __restrict__ C, int applyRope)
{
    extern __shared__ float sm[];
    float* As = sm;              // [2][BM][AST]
    float* Bs = sm + 2*ASZ;     // [2][BKC][BST]

    const int t    = threadIdx.x;
    const int lane = t & 31, wid = t >> 5;
    const int wm   = (wid >> 2) * 64;
    const int wn   = (wid & 3) * 32;
    const int m0   = blockIdx.y * BM, n0 = blockIdx.x * BN;
    const int lg   = lane >> 2, lc = lane & 3;

    // loader indices (A coalesced 8 lanes/row; B coalesced full rows)
    const int am  = t >> 3;   // m base 0..31 (+32*i)
    const int akq = t & 7;    // k quad
    const int bk  = t >> 5;   // k base 0..7 (+8*i)
    const int bn4 = t & 31;   // n quad

    const float* Aptr = A + (size_t)(m0 + am) * D_MODEL + 4*akq;
    const float* Wptr = W + (size_t)bk * D_MODEL + n0 + 4*bn4;

    float acc[4][4][4];
#pragma unroll
    for (int i = 0; i < 4; i++)
#pragma unroll
        for (int j = 0; j < 4; j++)
#pragma unroll
            for (int k = 0; k < 4; k++) acc[i][j][k] = 0.f;

    float4 pa[4], pb[4];
#pragma unroll
    for (int i = 0; i < 4; i++)
        pa[i] = *(const float4*)(Aptr + (size_t)(32*i) * D_MODEL);
#pragma unroll
    for (int i = 0; i < 4; i++)
        pb[i] = *(const float4*)(Wptr + (size_t)(8*i) * D_MODEL);

    int buf = 0;
    // STS chunk 0
    {
        float* Ad = As;
        float* Bd = Bs;
#pragma unroll
        for (int i = 0; i < 4; i++) {
            uint4 v; v.x = to_tf32(pa[i].x); v.y = to_tf32(pa[i].y);
                     v.z = to_tf32(pa[i].z); v.w = to_tf32(pa[i].w);
            *(uint4*)&Ad[(am + 32*i)*AST + 4*akq] = v;
        }
#pragma unroll
        for (int i = 0; i < 4; i++) {
            uint4 v; v.x = to_tf32(pb[i].x); v.y = to_tf32(pb[i].y);
                     v.z = to_tf32(pb[i].z); v.w = to_tf32(pb[i].w);
            *(uint4*)&Bd[(bk + 8*i)*BST + 4*bn4] = v;
        }
    }
    __syncthreads();

#pragma unroll 1
    for (int kc = 0; kc < D_MODEL / BKC; kc++) {
        const bool more = (kc + 1) < D_MODEL / BKC;
        if (more) {
            const size_t ko = (size_t)(kc + 1) * BKC;
#pragma unroll
            for (int i = 0; i < 4; i++)
                pa[i] = *(const float4*)(Aptr + (size_t)(32*i) * D_MODEL + ko);
#pragma unroll
            for (int i = 0; i < 4; i++)
                pb[i] = *(const float4*)(Wptr + (ko + 8*i) * D_MODEL);
        }

        const float* Ab = As + buf*ASZ;
        const float* Bb = Bs + buf*BSZ;
#pragma unroll
        for (int ks = 0; ks < 4; ks++) {
            unsigned af[4][4], bf[4][2];
#pragma unroll
            for (int mt = 0; mt < 4; mt++) {
                const float* ap = Ab + (wm + mt*16 + lg)*AST + ks*8 + lc;
                af[mt][0] = __float_as_uint(ap[0]);
                af[mt][1] = __float_as_uint(ap[8*AST]);
                af[mt][2] = __float_as_uint(ap[4]);
                af[mt][3] = __float_as_uint(ap[8*AST + 4]);
            }
#pragma unroll
            for (int nt = 0; nt < 4; nt++) {
                const float* bp = Bb + (ks*8 + lc)*BST + wn + nt*8 + lg;
                bf[nt][0] = __float_as_uint(bp[0]);
                bf[nt][1] = __float_as_uint(bp[4*BST]);
            }
#pragma unroll
            for (int mt = 0; mt < 4; mt++)
#pragma unroll
                for (int nt = 0; nt < 4; nt++)
                    mma_tf32(acc[mt][nt], af[mt], bf[nt]);
        }

        if (more) {
            float* Ad = As + (buf^1)*ASZ;
            float* Bd = Bs + (buf^1)*BSZ;
#pragma unroll
            for (int i = 0; i < 4; i++) {
                uint4 v; v.x = to_tf32(pa[i].x); v.y = to_tf32(pa[i].y);
                         v.z = to_tf32(pa[i].z); v.w = to_tf32(pa[i].w);
                *(uint4*)&Ad[(am + 32*i)*AST + 4*akq] = v;
            }
#pragma unroll
            for (int i = 0; i < 4; i++) {
                uint4 v; v.x = to_tf32(pb[i].x); v.y = to_tf32(pb[i].y);
                         v.z = to_tf32(pb[i].z); v.w = to_tf32(pb[i].w);
                *(uint4*)&Bd[(bk + 8*i)*BST + 4*bn4] = v;
            }
            __syncthreads();
            buf ^= 1;
        }
    }

    // Epilogue: bias + optional RoPE; acc pair (c0,c1)/(c2,c3) = adjacent cols.
    const float NEG_L2B = -0.02595256324130752f;   // -log2(10000)/512
#pragma unroll
    for (int nt = 0; nt < 4; nt++) {
        const int col = n0 + wn + nt*8 + 2*lc;
        const float b0 = bias[col], b1 = bias[col + 1];
        float fr = 0.f;
        if (applyRope) fr = exp2f((float)(col >> 1) * NEG_L2B);
#pragma unroll
        for (int mt = 0; mt < 4; mt++) {
#pragma unroll
            for (int hh = 0; hh < 2; hh++) {
                const int row = m0 + wm + mt*16 + lg + 8*hh;
                float v0 = acc[mt][nt][2*hh + 0] + b0;
                float v1 = acc[mt][nt][2*hh + 1] + b1;
                if (applyRope) {
                    float s, c;
                    sincosf((float)(row & (SEQ - 1)) * fr, &s, &c);
                    const float r0 = v0*c - v1*s;
                    v1 = v0*s + v1*c;
                    v0 = r0;
                }
                *(float2*)(C + (size_t)row * D_MODEL + col) = make_float2(v0, v1);
            }
        }
    }
}

// ===========================================================================
// Flash attention v2 (fp32, causal). 64x64 tiles, 256 threads.
// Thread = 4 rows (ty) x 4 cols (tx). Transposed Q/K/P in smem, stride 68.
// QK^T and PV: 2x float4 LDS per 16 FMA.
// ===========================================================================
#define FS 68
#define FLASH_SMEM (4*64*FS*4)

__global__ __launch_bounds__(256) void flash2(
    const float* __restrict__ Q, const float* __restrict__ K,
    const float* __restrict__ V, float* __restrict__ O)
{
    extern __shared__ float sm[];
    float* Qt = sm;                // [64 k][68]: Qt[kk][row]
    float* Kt = Qt + 64*FS;        // [64 k][68]: Kt[kk][col]
    float* Vs = Kt + 64*FS;        // [64 kt][68]: Vs[kt][hd]
    float* Pt = Vs + 64*FS;        // [64 kt][68]: Pt[kt][row]

    const int t  = threadIdx.x;
    const int tx = t & 15;         // col group
    const int ty = t >> 4;         // row group
    const int qt = blockIdx.x, h = blockIdx.y, b = blockIdx.z;
    const int q0 = qt * 64;

    const float* Qb = Q + (size_t)b * SEQ * D_MODEL + (size_t)h * HDIM;
    const float* Kb = K + (size_t)b * SEQ * D_MODEL + (size_t)h * HDIM;
    const float* Vb = V + (size_t)b * SEQ * D_MODEL + (size_t)h * HDIM;
    float*       Ob = O + (size_t)b * SEQ * D_MODEL + (size_t)h * HDIM;

    // Load Q transposed + scaled. r = t&63 (conflict-free scatter STS).
    {
        const int r = t & 63;
#pragma unroll
        for (int i = 0; i < 4; i++) {
            const int cq = (t >> 6) + 4*i;
            float4 v = *(const float4*)(Qb + (size_t)(q0 + r) * D_MODEL + 4*cq);
            Qt[(4*cq + 0)*FS + r] = v.x * 0.125f;
            Qt[(4*cq + 1)*FS + r] = v.y * 0.125f;
            Qt[(4*cq + 2)*FS + r] = v.z * 0.125f;
            Qt[(4*cq + 3)*FS + r] = v.w * 0.125f;
        }
    }

    float m_i[4], l_i[4], Oc[4][4];
#pragma unroll
    for (int i = 0; i < 4; i++) { m_i[i] = -1e30f; l_i[i] = 0.f; }
#pragma unroll
    for (int i = 0; i < 4; i++)
#pragma unroll
        for (int j = 0; j < 4; j++) Oc[i][j] = 0.f;

    for (int kt = 0; kt <= qt; kt++) {
        const int k0 = kt * 64;
        __syncthreads();
        // K transposed (scatter), V straight (coalesced float4)
        {
            const int r = t & 63;
#pragma unroll
            for (int i = 0; i < 4; i++) {
                const int cq = (t >> 6) + 4*i;
                float4 v = *(const float4*)(Kb + (size_t)(k0 + r) * D_MODEL + 4*cq);
                Kt[(4*cq + 0)*FS + r] = v.x;
                Kt[(4*cq + 1)*FS + r] = v.y;
                Kt[(4*cq + 2)*FS + r] = v.z;
                Kt[(4*cq + 3)*FS + r] = v.w;
            }
#pragma unroll
            for (int i = 0; i < 4; i++) {
                const int idx = t + 256*i;
                const int vr = idx >> 4, vq = idx & 15;
                float4 v = *(const float4*)(Vb + (size_t)(k0 + vr) * D_MODEL + 4*vq);
                *(float4*)&Vs[vr*FS + 4*vq] = v;
            }
        }
        __syncthreads();

        // S = Q K^T (4 rows x 4 cols per thread)
        float s[4][4];
#pragma unroll
        for (int i = 0; i < 4; i++)
#pragma unroll
            for (int j = 0; j < 4; j++) s[i][j] = 0.f;
#pragma unroll 8
        for (int kk = 0; kk < 64; kk++) {
            const float4 q4 = *(const float4*)(Qt + kk*FS + 4*ty);
            const float4 k4 = *(const float4*)(Kt + kk*FS + 4*tx);
            s[0][0] += q4.x*k4.x; s[0][1] += q4.x*k4.y; s[0][2] += q4.x*k4.z; s[0][3] += q4.x*k4.w;
            s[1][0] += q4.y*k4.x; s[1][1] += q4.y*k4.y; s[1][2] += q4.y*k4.z; s[1][3] += q4.y*k4.w;
            s[2][0] += q4.z*k4.x; s[2][1] += q4.z*k4.y; s[2][2] += q4.z*k4.z; s[2][3] += q4.z*k4.w;
            s[3][0] += q4.w*k4.x; s[3][1] += q4.w*k4.y; s[3][2] += q4.w*k4.z; s[3][3] += q4.w*k4.w;
        }

        if (kt == qt) {
#pragma unroll
            for (int i = 0; i < 4; i++)
#pragma unroll
                for (int j = 0; j < 4; j++)
                    if (k0 + 4*tx + j > q0 + 4*ty + i) s[i][j] = -1e30f;
        }

        // online softmax per row (reduce across 16 tx lanes: bits 0..3)
#pragma unroll
        for (int i = 0; i < 4; i++) {
            float mloc = fmaxf(fmaxf(s[i][0], s[i][1]), fmaxf(s[i][2], s[i][3]));
            mloc = fmaxf(mloc, __shfl_xor_sync(0xffffffffu, mloc, 1));
            mloc = fmaxf(mloc, __shfl_xor_sync(0xffffffffu, mloc, 2));
            mloc = fmaxf(mloc, __shfl_xor_sync(0xffffffffu, mloc, 4));
            mloc = fmaxf(mloc, __shfl_xor_sync(0xffffffffu, mloc, 8));
            const float m_new = fmaxf(m_i[i], mloc);
            const float alpha = __expf(m_i[i] - m_new);
            float sum = 0.f;
#pragma unroll
            for (int j = 0; j < 4; j++) { s[i][j] = __expf(s[i][j] - m_new); sum += s[i][j]; }
            sum += __shfl_xor_sync(0xffffffffu, sum, 1);
            sum += __shfl_xor_sync(0xffffffffu, sum, 2);
            sum += __shfl_xor_sync(0xffffffffu, sum, 4);
            sum += __shfl_xor_sync(0xffffffffu, sum, 8);
            l_i[i] = l_i[i]*alpha + sum;
            m_i[i] = m_new;
#pragma unroll
            for (int j = 0; j < 4; j++) Oc[i][j] *= alpha;
        }

        // stage P transposed: Pt[kt_col][row]
#pragma unroll
        for (int j = 0; j < 4; j++)
            *(float4*)(Pt + (4*tx + j)*FS + 4*ty) =
                make_float4(s[0][j], s[1][j], s[2][j], s[3][j]);
        __syncthreads();

        // O += P V
#pragma unroll 8
        for (int k2 = 0; k2 < 64; k2++) {
            const float4 p4 = *(const float4*)(Pt + k2*FS + 4*ty);
            const float4 v4 = *(const float4*)(Vs + k2*FS + 4*tx);
            Oc[0][0] += p4.x*v4.x; Oc[0][1] += p4.x*v4.y; Oc[0][2] += p4.x*v4.z; Oc[0][3] += p4.x*v4.w;
            Oc[1][0] += p4.y*v4.x; Oc[1][1] += p4.y*v4.y; Oc[1][2] += p4.y*v4.z; Oc[1][3] += p4.y*v4.w;
            Oc[2][0] += p4.z*v4.x; Oc[2][1] += p4.z*v4.y; Oc[2][2] += p4.z*v4.z; Oc[2][3] += p4.z*v4.w;
            Oc[3][0] += p4.w*v4.x; Oc[3][1] += p4.w*v4.y; Oc[3][2] += p4.w*v4.z; Oc[3][3] += p4.w*v4.w;
        }
    }

#pragma unroll
    for (int i = 0; i < 4; i++) {
        const float inv = 1.f / l_i[i];
        float4 o;
        o.x = Oc[i][0]*inv; o.y = Oc[i][1]*inv; o.z = Oc[i][2]*inv; o.w = Oc[i][3]*inv;
        *(float4*)(Ob + (size_t)(q0 + 4*ty + i) * D_MODEL + 4*tx) = o;
    }
}

// ===========================================================================
extern "C" void kernel_launch(void* const* d_in, const int* in_sizes, int n_in,
                              void* d_out, int out_size)
{
    const float* X  = (const float*)d_in[0];
    const float* Wq = (const float*)d_in[1];
    const float* bq = (const float*)d_in[2];
    const float* Wk = (const float*)d_in[3];
    const float* bk = (const float*)d_in[4];
    const float* Wv = (const float*)d_in[5];
    const float* bv = (const float*)d_in[6];
    const float* Wo = (const float*)d_in[7];
    const float* bo = (const float*)d_in[8];
    float* out = (float*)d_out;

    float *qp, *kp, *vp, *ap;
    cudaGetSymbolAddress((void**)&qp, g_Q);
    cudaGetSymbolAddress((void**)&kp, g_K);
    cudaGetSymbolAddress((void**)&vp, g_V);
    cudaGetSymbolAddress((void**)&ap, g_A);

    cudaFuncSetAttribute(gemm_tf32, cudaFuncAttributeMaxDynamicSharedMemorySize, GEMM_SMEM);
    cudaFuncSetAttribute(flash2,    cudaFuncAttributeMaxDynamicSharedMemorySize, FLASH_SMEM);

    dim3 gblk(D_MODEL / BN, MTOT / BM);
    gemm_tf32<<<gblk, 256, GEMM_SMEM>>>(X, Wq, bq, qp, 1);
    gemm_tf32<<<gblk, 256, GEMM_SMEM>>>(X, Wk, bk, kp, 1);
    gemm_tf32<<<gblk, 256, GEMM_SMEM>>>(X, Wv, bv, vp, 0);

    flash2<<<dim3(SEQ / 64, NHEADS, BATCH), 256, FLASH_SMEM>>>(qp, kp, vp, ap);

    gemm_tf32<<<gblk, 256, GEMM_SMEM>>>(ap, Wo, bo, out, 0);
}

// round 3
// speedup vs baseline: 6.9595x; 3.0024x over previous
#include <cuda_runtime.h>
#include <math.h>

#define D_MODEL 1024
#define SEQ     2048
#define NHEADS  16
#define HDIM    64
#define BATCH   4
#define MTOT    (BATCH*SEQ)

// Scratch (allocation-free rule: __device__ globals)
__device__ float g_Q[(size_t)MTOT * D_MODEL];
__device__ float g_K[(size_t)MTOT * D_MODEL];
__device__ float g_V[(size_t)MTOT * D_MODEL];
__device__ float g_A[(size_t)MTOT * D_MODEL];
__device__ float2 g_RT[(size_t)SEQ * 512];   // RoPE cos/sin table

__device__ __forceinline__ unsigned to_tf32(float x) {
    unsigned r; asm("cvt.rna.tf32.f32 %0, %1;" : "=r"(r) : "f"(x)); return r;
}
__device__ __forceinline__ void mma_tf32(float* d, const unsigned* a, const unsigned* b) {
    asm volatile(
        "mma.sync.aligned.m16n8k8.row.col.f32.tf32.tf32.f32 "
        "{%0,%1,%2,%3}, {%4,%5,%6,%7}, {%8,%9}, {%0,%1,%2,%3};\n"
        : "+f"(d[0]), "+f"(d[1]), "+f"(d[2]), "+f"(d[3])
        : "r"(a[0]), "r"(a[1]), "r"(a[2]), "r"(a[3]), "r"(b[0]), "r"(b[1]));
}

// exp2 on the FMA pipe (no MUFU). Valid for x <= ~0; clamps at -125.
__device__ __forceinline__ float fexp2(float x) {
    x = fmaxf(x, -125.f);
    float t = x + 12582912.f;                       // round-to-nearest-int magic
    int  ix = __float_as_int(t) - 0x4B400000;       // nearest int(x)
    float f = x - (t - 12582912.f);                 // frac in [-0.5, 0.5]
    float p = 1.3333558146e-3f;
    p = fmaf(p, f, 9.6181291076e-3f);
    p = fmaf(p, f, 5.5504108665e-2f);
    p = fmaf(p, f, 2.4022650696e-1f);
    p = fmaf(p, f, 6.9314718056e-1f);
    p = fmaf(p, f, 1.0f);
    return p * __int_as_float((ix + 127) << 23);
}

// ===========================================================================
// RoPE table: g_RT[pos*512 + p] = (cos, sin)(pos * 10000^(-p/512))
// ===========================================================================
__global__ __launch_bounds__(256) void rope_table() {
    const int i = blockIdx.x * 256 + threadIdx.x;   // 0 .. 2048*512-1
    const int pos = i >> 9, p = i & 511;
    const float NEG_L2B = -0.02595256324130752f;    // -log2(10000)/512
    const float fr = exp2f((float)p * NEG_L2B);
    float s, c; sincosf((float)pos * fr, &s, &c);
    g_RT[i] = make_float2(c, s);
}

// ===========================================================================
// tf32 tensor-core GEMM: C[M,1024] = A[M,1024] @ W[1024,1024] + bias (+RoPE)
// ===========================================================================
#define BM 128
#define BN 128
#define BKC 32
#define AST 36
#define BST 136
#define ASZ (BM*AST)
#define BSZ (BKC*BST)
#define GEMM_SMEM ((2*ASZ + 2*BSZ)*4)

__global__ __launch_bounds__(256) void gemm_tf32(
    const float* __restrict__ A, const float* __restrict__ W,
    const float* __restrict__ bias, float* __restrict__ C, int applyRope)
{
    extern __shared__ float sm[];
    float* As = sm;
    float* Bs = sm + 2*ASZ;

    const int t    = threadIdx.x;
    const int lane = t & 31, wid = t >> 5;
    const int wm   = (wid >> 2) * 64;
    const int wn   = (wid & 3) * 32;
    const int m0   = blockIdx.y * BM, n0 = blockIdx.x * BN;
    const int lg   = lane >> 2, lc = lane & 3;

    const int am  = t >> 3;
    const int akq = t & 7;
    const int bk  = t >> 5;
    const int bn4 = t & 31;

    const float* Aptr = A + (size_t)(m0 + am) * D_MODEL + 4*akq;
    const float* Wptr = W + (size_t)bk * D_MODEL + n0 + 4*bn4;

    float acc[4][4][4];
#pragma unroll
    for (int i = 0; i < 4; i++)
#pragma unroll
        for (int j = 0; j < 4; j++)
#pragma unroll
            for (int k = 0; k < 4; k++) acc[i][j][k] = 0.f;

    float4 pa[4], pb[4];
#pragma unroll
    for (int i = 0; i < 4; i++)
        pa[i] = *(const float4*)(Aptr + (size_t)(32*i) * D_MODEL);
#pragma unroll
    for (int i = 0; i < 4; i++)
        pb[i] = *(const float4*)(Wptr + (size_t)(8*i) * D_MODEL);

    int buf = 0;
    {
        float* Ad = As;
        float* Bd = Bs;
#pragma unroll
        for (int i = 0; i < 4; i++) {
            uint4 v; v.x = to_tf32(pa[i].x); v.y = to_tf32(pa[i].y);
                     v.z = to_tf32(pa[i].z); v.w = to_tf32(pa[i].w);
            *(uint4*)&Ad[(am + 32*i)*AST + 4*akq] = v;
        }
#pragma unroll
        for (int i = 0; i < 4; i++) {
            uint4 v; v.x = to_tf32(pb[i].x); v.y = to_tf32(pb[i].y);
                     v.z = to_tf32(pb[i].z); v.w = to_tf32(pb[i].w);
            *(uint4*)&Bd[(bk + 8*i)*BST + 4*bn4] = v;
        }
    }
    __syncthreads();

#pragma unroll 1
    for (int kc = 0; kc < D_MODEL / BKC; kc++) {
        const bool more = (kc + 1) < D_MODEL / BKC;
        if (more) {
            const size_t ko = (size_t)(kc + 1) * BKC;
#pragma unroll
            for (int i = 0; i < 4; i++)
                pa[i] = *(const float4*)(Aptr + (size_t)(32*i) * D_MODEL + ko);
#pragma unroll
            for (int i = 0; i < 4; i++)
                pb[i] = *(const float4*)(Wptr + (ko + 8*i) * D_MODEL);
        }

        const float* Ab = As + buf*ASZ;
        const float* Bb = Bs + buf*BSZ;
#pragma unroll
        for (int ks = 0; ks < 4; ks++) {
            unsigned af[4][4], bf[4][2];
#pragma unroll
            for (int mt = 0; mt < 4; mt++) {
                const float* ap = Ab + (wm + mt*16 + lg)*AST + ks*8 + lc;
                af[mt][0] = __float_as_uint(ap[0]);
                af[mt][1] = __float_as_uint(ap[8*AST]);
                af[mt][2] = __float_as_uint(ap[4]);
                af[mt][3] = __float_as_uint(ap[8*AST + 4]);
            }
#pragma unroll
            for (int nt = 0; nt < 4; nt++) {
                const float* bp = Bb + (ks*8 + lc)*BST + wn + nt*8 + lg;
                bf[nt][0] = __float_as_uint(bp[0]);
                bf[nt][1] = __float_as_uint(bp[4*BST]);
            }
#pragma unroll
            for (int mt = 0; mt < 4; mt++)
#pragma unroll
                for (int nt = 0; nt < 4; nt++)
                    mma_tf32(acc[mt][nt], af[mt], bf[nt]);
        }

        if (more) {
            float* Ad = As + (buf^1)*ASZ;
            float* Bd = Bs + (buf^1)*BSZ;
#pragma unroll
            for (int i = 0; i < 4; i++) {
                uint4 v; v.x = to_tf32(pa[i].x); v.y = to_tf32(pa[i].y);
                         v.z = to_tf32(pa[i].z); v.w = to_tf32(pa[i].w);
                *(uint4*)&Ad[(am + 32*i)*AST + 4*akq] = v;
            }
#pragma unroll
            for (int i = 0; i < 4; i++) {
                uint4 v; v.x = to_tf32(pb[i].x); v.y = to_tf32(pb[i].y);
                         v.z = to_tf32(pb[i].z); v.w = to_tf32(pb[i].w);
                *(uint4*)&Bd[(bk + 8*i)*BST + 4*bn4] = v;
            }
            __syncthreads();
            buf ^= 1;
        }
    }

    // Epilogue: bias + optional RoPE (table-based, no MUFU).
#pragma unroll
    for (int nt = 0; nt < 4; nt++) {
        const int col = n0 + wn + nt*8 + 2*lc;
        const float b0 = bias[col], b1 = bias[col + 1];
        const float2* rt = &g_RT[(size_t)(col >> 1)];
#pragma unroll
        for (int mt = 0; mt < 4; mt++) {
#pragma unroll
            for (int hh = 0; hh < 2; hh++) {
                const int row = m0 + wm + mt*16 + lg + 8*hh;
                float v0 = acc[mt][nt][2*hh + 0] + b0;
                float v1 = acc[mt][nt][2*hh + 1] + b1;
                if (applyRope) {
                    const float2 cs = rt[(size_t)(row & (SEQ-1)) * 512];
                    const float r0 = v0*cs.x - v1*cs.y;
                    v1 = v0*cs.y + v1*cs.x;
                    v0 = r0;
                }
                *(float2*)(C + (size_t)row * D_MODEL + col) = make_float2(v0, v1);
            }
        }
    }
}

// ===========================================================================
// Flash attention v3: tf32 tensor cores. 256 thr (8 warps), BM=128, BN=64.
// Each warp owns a 16-row stripe. P staged per-warp in smem (no block sync).
// Q pre-scaled by log2(e)/8 -> softmax in base-2 via FMA-pipe exp2.
// ===========================================================================
#define FBM 128
#define FBN 64
#define QST 68
#define KST 68
#define VST 72
#define PST 68
#define FLASH_SMEM ((FBM*QST + FBN*KST + FBN*VST + FBM*PST) * 4)

__global__ __launch_bounds__(256, 2) void flash3(
    const float* __restrict__ Q, const float* __restrict__ K,
    const float* __restrict__ V, float* __restrict__ O)
{
    extern __shared__ float sm[];
    float* Qs = sm;                    // [128][QST] tf32, pre-scaled
    float* Ks = Qs + FBM*QST;          // [64][KST]  tf32
    float* Vs = Ks + FBN*KST;          // [64][VST]  tf32
    float* Ps = Vs + FBN*VST;          // [128][PST] tf32 (per-warp stripes)

    const int t = threadIdx.x, lane = t & 31, w = t >> 5;
    const int lg = lane >> 2, lc = lane & 3;
    const int wm = w * 16;
    const int qt = blockIdx.x, h = blockIdx.y, b = blockIdx.z;
    const int q0 = qt * FBM;

    const float* Qb = Q + (size_t)b * SEQ * D_MODEL + (size_t)h * HDIM;
    const float* Kb = K + (size_t)b * SEQ * D_MODEL + (size_t)h * HDIM;
    const float* Vb = V + (size_t)b * SEQ * D_MODEL + (size_t)h * HDIM;
    float*       Ob = O + (size_t)b * SEQ * D_MODEL + (size_t)h * HDIM;

    // Load Q tile (scale by log2e/8, convert tf32)
    const float QSC = 0.125f * 1.4426950408889634f;
#pragma unroll
    for (int i = 0; i < 8; i++) {
        const int idx = t + 256*i;
        const int r = idx >> 4, q = idx & 15;
        float4 v = *(const float4*)(Qb + (size_t)(q0 + r) * D_MODEL + 4*q);
        uint4 u; u.x = to_tf32(v.x*QSC); u.y = to_tf32(v.y*QSC);
                 u.z = to_tf32(v.z*QSC); u.w = to_tf32(v.w*QSC);
        *(uint4*)&Qs[r*QST + 4*q] = u;
    }

    float accO[8][4];
#pragma unroll
    for (int i = 0; i < 8; i++)
#pragma unroll
        for (int j = 0; j < 4; j++) accO[i][j] = 0.f;
    float m0 = -1e30f, m1 = -1e30f, l0 = 0.f, l1 = 0.f;

    const int ntiles = 2*qt + 2;
#pragma unroll 1
    for (int kt = 0; kt < ntiles; kt++) {
        const int k0 = kt * FBN;
        __syncthreads();
#pragma unroll
        for (int i = 0; i < 4; i++) {
            const int idx = t + 256*i;
            const int r = idx >> 4, q = idx & 15;
            float4 kv = *(const float4*)(Kb + (size_t)(k0 + r) * D_MODEL + 4*q);
            uint4 uk; uk.x = to_tf32(kv.x); uk.y = to_tf32(kv.y);
                      uk.z = to_tf32(kv.z); uk.w = to_tf32(kv.w);
            *(uint4*)&Ks[r*KST + 4*q] = uk;
            float4 vv = *(const float4*)(Vb + (size_t)(k0 + r) * D_MODEL + 4*q);
            uint4 uv; uv.x = to_tf32(vv.x); uv.y = to_tf32(vv.y);
                      uv.z = to_tf32(vv.z); uv.w = to_tf32(vv.w);
            *(uint4*)&Vs[r*VST + 4*q] = uv;
        }
        __syncthreads();

        if (k0 <= q0 + wm + 15) {   // not fully masked for this warp
            // ---- S = Q K^T ----
            float accS[8][4];
#pragma unroll
            for (int i = 0; i < 8; i++)
#pragma unroll
                for (int j = 0; j < 4; j++) accS[i][j] = 0.f;
#pragma unroll
            for (int k8 = 0; k8 < 8; k8++) {
                unsigned a[4];
                const float* ap = Qs + (wm + lg)*QST + k8*8 + lc;
                a[0] = __float_as_uint(ap[0]);
                a[1] = __float_as_uint(ap[8*QST]);
                a[2] = __float_as_uint(ap[4]);
                a[3] = __float_as_uint(ap[8*QST + 4]);
#pragma unroll
                for (int nt = 0; nt < 8; nt++) {
                    unsigned bfr[2];
                    const float* bp = Ks + (nt*8 + lg)*KST + k8*8 + lc;
                    bfr[0] = __float_as_uint(bp[0]);
                    bfr[1] = __float_as_uint(bp[4]);
                    mma_tf32(accS[nt], a, bfr);
                }
            }

            // ---- causal mask (diagonal tiles only) ----
            if (k0 + 63 > q0 + wm) {
                const int r0g = q0 + wm + lg, r1g = r0g + 8;
#pragma unroll
                for (int nt = 0; nt < 8; nt++) {
                    const int c = k0 + nt*8 + 2*lc;
                    if (c     > r0g) accS[nt][0] = -1e30f;
                    if (c + 1 > r0g) accS[nt][1] = -1e30f;
                    if (c     > r1g) accS[nt][2] = -1e30f;
                    if (c + 1 > r1g) accS[nt][3] = -1e30f;
                }
            }

            // ---- online softmax (base-2 domain) ----
            float mx0 = -1e30f, mx1 = -1e30f;
#pragma unroll
            for (int nt = 0; nt < 8; nt++) {
                mx0 = fmaxf(mx0, fmaxf(accS[nt][0], accS[nt][1]));
                mx1 = fmaxf(mx1, fmaxf(accS[nt][2], accS[nt][3]));
            }
            mx0 = fmaxf(mx0, __shfl_xor_sync(0xffffffffu, mx0, 1));
            mx0 = fmaxf(mx0, __shfl_xor_sync(0xffffffffu, mx0, 2));
            mx1 = fmaxf(mx1, __shfl_xor_sync(0xffffffffu, mx1, 1));
            mx1 = fmaxf(mx1, __shfl_xor_sync(0xffffffffu, mx1, 2));
            const float mn0 = fmaxf(m0, mx0), mn1 = fmaxf(m1, mx1);
            const float al0 = fexp2(m0 - mn0), al1 = fexp2(m1 - mn1);
            float s0 = 0.f, s1 = 0.f;
#pragma unroll
            for (int nt = 0; nt < 8; nt++) {
                accS[nt][0] = fexp2(accS[nt][0] - mn0);
                accS[nt][1] = fexp2(accS[nt][1] - mn0);
                accS[nt][2] = fexp2(accS[nt][2] - mn1);
                accS[nt][3] = fexp2(accS[nt][3] - mn1);
                s0 += accS[nt][0] + accS[nt][1];
                s1 += accS[nt][2] + accS[nt][3];
            }
            s0 += __shfl_xor_sync(0xffffffffu, s0, 1);
            s0 += __shfl_xor_sync(0xffffffffu, s0, 2);
            s1 += __shfl_xor_sync(0xffffffffu, s1, 1);
            s1 += __shfl_xor_sync(0xffffffffu, s1, 2);
            l0 = l0*al0 + s0;  l1 = l1*al1 + s1;
            m0 = mn0;          m1 = mn1;
#pragma unroll
            for (int nt = 0; nt < 8; nt++) {
                accO[nt][0] *= al0; accO[nt][1] *= al0;
                accO[nt][2] *= al1; accO[nt][3] *= al1;
            }

            // ---- stage P (tf32) into this warp's private stripe ----
#pragma unroll
            for (int nt = 0; nt < 8; nt++) {
                float2 p01, p23;
                p01.x = __uint_as_float(to_tf32(accS[nt][0]));
                p01.y = __uint_as_float(to_tf32(accS[nt][1]));
                p23.x = __uint_as_float(to_tf32(accS[nt][2]));
                p23.y = __uint_as_float(to_tf32(accS[nt][3]));
                *(float2*)&Ps[(wm + lg    )*PST + nt*8 + 2*lc] = p01;
                *(float2*)&Ps[(wm + lg + 8)*PST + nt*8 + 2*lc] = p23;
            }
            __syncwarp();

            // ---- O += P V ----
#pragma unroll
            for (int k8 = 0; k8 < 8; k8++) {
                unsigned a[4];
                const float* ap = Ps + (wm + lg)*PST + k8*8 + lc;
                a[0] = __float_as_uint(ap[0]);
                a[1] = __float_as_uint(ap[8*PST]);
                a[2] = __float_as_uint(ap[4]);
                a[3] = __float_as_uint(ap[8*PST + 4]);
#pragma unroll
                for (int nt = 0; nt < 8; nt++) {
                    unsigned bfr[2];
                    const float* bp = Vs + (k8*8 + lc)*VST + nt*8 + lg;
                    bfr[0] = __float_as_uint(bp[0]);
                    bfr[1] = __float_as_uint(bp[4*VST]);
                    mma_tf32(accO[nt], a, bfr);
                }
            }
        }
    }

    // ---- epilogue ----
    const float inv0 = 1.f / l0, inv1 = 1.f / l1;
    const int r0g = q0 + wm + lg, r1g = r0g + 8;
#pragma unroll
    for (int nt = 0; nt < 8; nt++) {
        const int col = nt*8 + 2*lc;
        *(float2*)(Ob + (size_t)r0g * D_MODEL + col) =
            make_float2(accO[nt][0]*inv0, accO[nt][1]*inv0);
        *(float2*)(Ob + (size_t)r1g * D_MODEL + col) =
            make_float2(accO[nt][2]*inv1, accO[nt][3]*inv1);
    }
}

// ===========================================================================
extern "C" void kernel_launch(void* const* d_in, const int* in_sizes, int n_in,
                              void* d_out, int out_size)
{
    const float* X  = (const float*)d_in[0];
    const float* Wq = (const float*)d_in[1];
    const float* bq = (const float*)d_in[2];
    const float* Wk = (const float*)d_in[3];
    const float* bk = (const float*)d_in[4];
    const float* Wv = (const float*)d_in[5];
    const float* bv = (const float*)d_in[6];
    const float* Wo = (const float*)d_in[7];
    const float* bo = (const float*)d_in[8];
    float* out = (float*)d_out;

    float *qp, *kp, *vp, *ap;
    cudaGetSymbolAddress((void**)&qp, g_Q);
    cudaGetSymbolAddress((void**)&kp, g_K);
    cudaGetSymbolAddress((void**)&vp, g_V);
    cudaGetSymbolAddress((void**)&ap, g_A);

    cudaFuncSetAttribute(gemm_tf32, cudaFuncAttributeMaxDynamicSharedMemorySize, GEMM_SMEM);
    cudaFuncSetAttribute(flash3,    cudaFuncAttributeMaxDynamicSharedMemorySize, FLASH_SMEM);

    rope_table<<<SEQ*512/256, 256>>>();

    dim3 gblk(D_MODEL / BN, MTOT / BM);
    gemm_tf32<<<gblk, 256, GEMM_SMEM>>>(X, Wq, bq, qp, 1);
    gemm_tf32<<<gblk, 256, GEMM_SMEM>>>(X, Wk, bk, kp, 1);
    gemm_tf32<<<gblk, 256, GEMM_SMEM>>>(X, Wv, bv, vp, 0);

    flash3<<<dim3(SEQ / FBM, NHEADS, BATCH), 256, FLASH_SMEM>>>(qp, kp, vp, ap);

    gemm_tf32<<<gblk, 256, GEMM_SMEM>>>(ap, Wo, bo, out, 0);
}